// round 12
// baseline (speedup 1.0000x reference)
#include <cuda_runtime.h>
#include <cuda_fp16.h>
#include <cstdint>

// Problem dims (fixed by the reference)
#define NE 8
#define NT 1024
#define ND 2048
#define NI 4096

// ---------------------------------------------------------------------------
// __device__ scratch (alloc-free rule): fp16 copies of inputs + intermediate H
// Weight fp16 buffers are filled by the GEMM kernels' own prologues.
// ---------------------------------------------------------------------------
__device__ __half g_xh [(size_t)NE * NT * ND];   //  32 MB
__device__ __half g_gwh[(size_t)NE * ND * NI];   // 134 MB
__device__ __half g_iwh[(size_t)NE * ND * NI];   // 134 MB
__device__ __half g_owh[(size_t)NE * NI * ND];   // 134 MB
__device__ __half g_H  [(size_t)NE * NT * NI];   //  67 MB

// ---------------------------------------------------------------------------
// PTX helpers (baseline sm_80+ instructions only — compute_103-safe)
// ---------------------------------------------------------------------------
__device__ __forceinline__ uint32_t smem_u32(const void* p) {
    uint32_t a;
    asm("{ .reg .u64 t; cvta.to.shared.u64 t, %1; cvt.u32.u64 %0, t; }"
        : "=r"(a) : "l"(p));
    return a;
}
__device__ __forceinline__ void cp16(uint32_t saddr, const void* g) {
    asm volatile("cp.async.cg.shared.global [%0], [%1], 16;"
                 :: "r"(saddr), "l"(g) : "memory");
}
__device__ __forceinline__ void cp_commit() {
    asm volatile("cp.async.commit_group;" ::: "memory");
}
template <int N> __device__ __forceinline__ void cp_wait() {
    asm volatile("cp.async.wait_group %0;" :: "n"(N) : "memory");
}
__device__ __forceinline__ void ldsm4(uint32_t* r, uint32_t a) {
    asm volatile("ldmatrix.sync.aligned.m8n8.x4.shared.b16 {%0,%1,%2,%3}, [%4];"
                 : "=r"(r[0]), "=r"(r[1]), "=r"(r[2]), "=r"(r[3]) : "r"(a));
}
__device__ __forceinline__ void ldsm4t(uint32_t* r, uint32_t a) {
    asm volatile("ldmatrix.sync.aligned.m8n8.x4.trans.shared.b16 {%0,%1,%2,%3}, [%4];"
                 : "=r"(r[0]), "=r"(r[1]), "=r"(r[2]), "=r"(r[3]) : "r"(a));
}
__device__ __forceinline__ void mma16816(float* c, const uint32_t* a,
                                         uint32_t b0, uint32_t b1) {
    asm volatile(
        "mma.sync.aligned.m16n8k16.row.col.f32.f16.f16.f32 "
        "{%0,%1,%2,%3}, {%4,%5,%6,%7}, {%8,%9}, {%0,%1,%2,%3};"
        : "+f"(c[0]), "+f"(c[1]), "+f"(c[2]), "+f"(c[3])
        : "r"(a[0]), "r"(a[1]), "r"(a[2]), "r"(a[3]), "r"(b0), "r"(b1));
}
__device__ __forceinline__ uint32_t h2u(float lo, float hi) {
    __half2 h = __floats2half2_rn(lo, hi);
    return *(uint32_t*)&h;
}
#define SWZ(b) ((b) ^ (((b) >> 3) & 0x70))   // SW128: conflict-free ldmatrix

// ---------------------------------------------------------------------------
// Kernel 0: fp32 -> fp16 conversion for x (grid-stride; streaming)
// ---------------------------------------------------------------------------
__global__ void cvt_f2h(const float* __restrict__ s, __half* __restrict__ d,
                        size_t n)
{
    size_t i = ((size_t)blockIdx.x * blockDim.x + threadIdx.x) * 8;
    size_t stride = (size_t)gridDim.x * blockDim.x * 8;
    for (; i < n; i += stride) {
        float4 v0 = __ldcs((const float4*)(s + i));
        float4 v1 = __ldcs((const float4*)(s + i + 4));
        uint4 o;
        o.x = h2u(v0.x, v0.y); o.y = h2u(v0.z, v0.w);
        o.z = h2u(v1.x, v1.y); o.w = h2u(v1.z, v1.w);
        __stcs((uint4*)(d + i), o);
    }
}

// ===========================================================================
// Kernel 1: fused dual GEMM + GLU with embedded weight conversion.
//   Prologue: block converts its fp32 B-strip (gw+iw cols n0..n0+63) to fp16
//   in g_gwh/g_iwh. All 8 sibling m-blocks convert the same strip redundantly
//   (identical values -> benign race; L2 dedups the fp32 reads).
//   Mainloop: R10 structure (two barriers, loads after MMA block).
//   BM=128, BN=64, BK=64, 3-stage cp.async, 8 warps; smem 96KB; 2 CTAs/SM.
// ===========================================================================
__global__ __launch_bounds__(256, 2)
void glu_mma_kernel(const float* __restrict__ gw, const float* __restrict__ iw)
{
    extern __shared__ char smem[];
    const uint32_t sb = smem_u32(smem);
    const int tid = threadIdx.x, warp = tid >> 5, lane = tid & 31;
    const int wm = warp & 3, wn = warp >> 2;
    const int m0 = blockIdx.x * 128, n0 = blockIdx.y * 64, e = blockIdx.z;

    // ---- Prologue: convert B strip [ND, 64] of gw and iw to fp16 ----
    {
        const float* Gs = gw + (size_t)e * ND * NI + n0;
        const float* Us = iw + (size_t)e * ND * NI + n0;
        __half* Gd = g_gwh + (size_t)e * ND * NI + n0;
        __half* Ud = g_iwh + (size_t)e * ND * NI + n0;
        #pragma unroll 4
        for (int i = 0; i < 128; i++) {           // 2048 rows x 16 float4
            int f = tid + i * 256;
            int r = f >> 4, c4 = (f & 15) << 2;
            size_t off = (size_t)r * NI + c4;
            float4 vg = *(const float4*)(Gs + off);
            float4 vu = *(const float4*)(Us + off);
            uint2 og = make_uint2(h2u(vg.x, vg.y), h2u(vg.z, vg.w));
            uint2 ou = make_uint2(h2u(vu.x, vu.y), h2u(vu.z, vu.w));
            *(uint2*)(Gd + off) = og;
            *(uint2*)(Ud + off) = ou;
        }
        __threadfence();       // own writes visible to own cp.async (via L2)
        __syncthreads();
    }

    const __half* Ab = g_xh  + ((size_t)e * NT + m0) * ND;
    const __half* Gb = g_gwh + ((size_t)e * ND) * NI + n0;
    const __half* Ub = g_iwh + ((size_t)e * ND) * NI + n0;

    // per-thread ldmatrix byte offsets (pre-swizzle)
    int aoff[2], boff[2];
    #pragma unroll
    for (int i = 0; i < 2; i++)
        aoff[i] = (wm * 32 + i * 16 + (lane & 15)) * 128 + (lane >> 4) * 16;
    #pragma unroll
    for (int j = 0; j < 2; j++)
        boff[j] = (lane & 15) * 128 + (wn * 32 + j * 16 + (lane >> 4) * 8) * 2;

    float accG[2][4][4] = {}, accU[2][4][4] = {};

    auto load_stage = [&](int kt, int s) {
        const uint32_t sbase = sb + s * 32768;
        const int k0 = kt * 64;
        #pragma unroll
        for (int i = 0; i < 4; i++) {            // A: 128x64 halves
            int f = tid + i * 256, r = f >> 3, c = (f & 7) * 8;
            cp16(sbase + SWZ(r * 128 + c * 2), Ab + (size_t)r * ND + k0 + c);
        }
        #pragma unroll
        for (int i = 0; i < 2; i++) {            // Bg/Bu: 64x64 halves each
            int f = tid + i * 256, r = f >> 3, c = (f & 7) * 8;
            size_t go = (size_t)(k0 + r) * NI + c;
            cp16(sbase + 16384 + SWZ(r * 128 + c * 2), Gb + go);
            cp16(sbase + 24576 + SWZ(r * 128 + c * 2), Ub + go);
        }
    };

    constexpr int KT = ND / 64;   // 32
    load_stage(0, 0); cp_commit();
    load_stage(1, 1); cp_commit();

    for (int kt = 0; kt < KT; ++kt) {
        cp_wait<1>();
        __syncthreads();
        const int s = kt % 3;
        const uint32_t sA = sb + s * 32768, sBg = sA + 16384, sBu = sA + 24576;
        #pragma unroll
        for (int kk = 0; kk < 4; ++kk) {
            uint32_t a[2][4], bg[2][4], bu[2][4];
            #pragma unroll
            for (int i = 0; i < 2; i++) ldsm4(a[i], sA + SWZ(aoff[i] + kk * 32));
            #pragma unroll
            for (int j = 0; j < 2; j++) {
                ldsm4t(bg[j], sBg + SWZ(boff[j] + kk * 2048));
                ldsm4t(bu[j], sBu + SWZ(boff[j] + kk * 2048));
            }
            #pragma unroll
            for (int i = 0; i < 2; i++)
                #pragma unroll
                for (int j = 0; j < 4; j++) {
                    mma16816(accG[i][j], a[i], bg[j >> 1][(j & 1) * 2],
                             bg[j >> 1][(j & 1) * 2 + 1]);
                    mma16816(accU[i][j], a[i], bu[j >> 1][(j & 1) * 2],
                             bu[j >> 1][(j & 1) * 2 + 1]);
                }
        }
        __syncthreads();
        if (kt + 2 < KT) load_stage(kt + 2, (kt + 2) % 3);
        cp_commit();
    }

    // Epilogue: H = silu(G)*U, fp16 store. c-frag: rows lane>>2 (+8), cols 2*(lane&3).
    __half* Hd = g_H + (size_t)e * NT * NI;
    const int rb = m0 + wm * 32 + (lane >> 2);
    const int cb = n0 + wn * 32 + (lane & 3) * 2;
    #pragma unroll
    for (int i = 0; i < 2; i++)
        #pragma unroll
        for (int j = 0; j < 4; j++)
            #pragma unroll
            for (int h = 0; h < 2; h++) {   // h=0: row, h=1: row+8
                float g0 = accG[i][j][h * 2],     u0 = accU[i][j][h * 2];
                float g1 = accG[i][j][h * 2 + 1], u1 = accU[i][j][h * 2 + 1];
                float h0 = (g0 / (1.0f + __expf(-g0))) * u0;
                float h1 = (g1 / (1.0f + __expf(-g1))) * u1;
                size_t off = (size_t)(rb + i * 16 + h * 8) * NI + cb + j * 8;
                *(__half2*)(Hd + off) = __floats2half2_rn(h0, h1);
            }
}

// ===========================================================================
// Kernel 2: out = H @ op with embedded ow conversion (same strip scheme).
//   BM=128, BN=128, BK=64, 3 stages, 8 warps; smem 96KB; 2 CTAs/SM.
// ===========================================================================
__global__ __launch_bounds__(256, 2)
void out_mma_kernel(const float* __restrict__ ow, float* __restrict__ out)
{
    extern __shared__ char smem[];
    const uint32_t sb = smem_u32(smem);
    const int tid = threadIdx.x, warp = tid >> 5, lane = tid & 31;
    const int wm = warp & 3, wn = warp >> 2;
    const int m0 = blockIdx.x * 128, n0 = blockIdx.y * 128, e = blockIdx.z;

    // ---- Prologue: convert ow strip [NI, 128] to fp16 ----
    {
        const float* Os = ow + (size_t)e * NI * ND + n0;
        __half* Od = g_owh + (size_t)e * NI * ND + n0;
        #pragma unroll 4
        for (int i = 0; i < 512; i++) {           // 4096 rows x 32 float4
            int f = tid + i * 256;
            int r = f >> 5, c4 = (f & 31) << 2;
            size_t off = (size_t)r * ND + c4;
            float4 v = *(const float4*)(Os + off);
            uint2 o = make_uint2(h2u(v.x, v.y), h2u(v.z, v.w));
            *(uint2*)(Od + off) = o;
        }
        __threadfence();
        __syncthreads();
    }

    const __half* Ab = g_H   + ((size_t)e * NT + m0) * NI;
    const __half* Bb = g_owh + ((size_t)e * NI) * ND + n0;

    int aoff[2];
    #pragma unroll
    for (int i = 0; i < 2; i++)
        aoff[i] = (wm * 32 + i * 16 + (lane & 15)) * 128 + (lane >> 4) * 16;
    // B: [64 k][128 n] stored as two [64][64] halves (128B rows each)
    int bhalf[4], boff[4];
    #pragma unroll
    for (int j = 0; j < 4; j++) {
        int c = wn * 64 + j * 16 + (lane >> 4) * 8;
        bhalf[j] = (c >> 6) * 8192;
        boff[j]  = (lane & 15) * 128 + (c & 63) * 2;
    }

    float acc[2][8][4] = {};

    auto load_stage = [&](int kt, int s) {
        const uint32_t sbase = sb + s * 32768;
        const int k0 = kt * 64;
        #pragma unroll
        for (int i = 0; i < 4; i++) {            // A: 128x64
            int f = tid + i * 256, r = f >> 3, c = (f & 7) * 8;
            cp16(sbase + SWZ(r * 128 + c * 2), Ab + (size_t)r * NI + k0 + c);
        }
        #pragma unroll
        for (int i = 0; i < 4; i++) {            // B: 64x128
            int f = tid + i * 256, r = f >> 4, c = (f & 15) * 8;
            cp16(sbase + 16384 + (c >> 6) * 8192 + SWZ(r * 128 + (c & 63) * 2),
                 Bb + (size_t)(k0 + r) * ND + c);
        }
    };

    constexpr int KT = NI / 64;   // 64
    load_stage(0, 0); cp_commit();
    load_stage(1, 1); cp_commit();

    for (int kt = 0; kt < KT; ++kt) {
        cp_wait<1>();
        __syncthreads();
        const int s = kt % 3;
        const uint32_t sA = sb + s * 32768, sB = sA + 16384;
        #pragma unroll
        for (int kk = 0; kk < 4; ++kk) {
            uint32_t a[2][4], b[4][4];
            #pragma unroll
            for (int i = 0; i < 2; i++) ldsm4(a[i], sA + SWZ(aoff[i] + kk * 32));
            #pragma unroll
            for (int j = 0; j < 4; j++)
                ldsm4t(b[j], sB + bhalf[j] + SWZ(boff[j] + kk * 2048));
            #pragma unroll
            for (int i = 0; i < 2; i++)
                #pragma unroll
                for (int j = 0; j < 8; j++)
                    mma16816(acc[i][j], a[i], b[j >> 1][(j & 1) * 2],
                             b[j >> 1][(j & 1) * 2 + 1]);
        }
        __syncthreads();
        if (kt + 2 < KT) load_stage(kt + 2, (kt + 2) % 3);
        cp_commit();
    }

    // Epilogue: fp32 stores
    float* Od = out + (size_t)e * NT * ND;
    const int rb = m0 + wm * 32 + (lane >> 2);
    const int cb = n0 + wn * 64 + (lane & 3) * 2;
    #pragma unroll
    for (int i = 0; i < 2; i++)
        #pragma unroll
        for (int j = 0; j < 8; j++)
            #pragma unroll
            for (int h = 0; h < 2; h++) {
                size_t off = (size_t)(rb + i * 16 + h * 8) * ND + cb + j * 8;
                float2 v = make_float2(acc[i][j][h * 2], acc[i][j][h * 2 + 1]);
                *(float2*)(Od + off) = v;
            }
}

// ---------------------------------------------------------------------------
// Harness entry. Inputs: x, gate_proj, inner_proj, output_proj (all fp32).
// Sequence: cvt x -> GEMM1 (GLU + gw/iw convert) -> GEMM2 (+ ow convert).
// All graph-capturable, no allocations.
// ---------------------------------------------------------------------------
extern "C" void kernel_launch(void* const* d_in, const int* in_sizes, int n_in,
                              void* d_out, int out_size)
{
    const float* x  = (const float*)d_in[0];
    const float* gw = (const float*)d_in[1];
    const float* iw = (const float*)d_in[2];
    const float* ow = (const float*)d_in[3];
    float* out = (float*)d_out;

    __half* xh;
    cudaGetSymbolAddress((void**)&xh, g_xh);

    cvt_f2h<<<2048, 256>>>(x, xh, (size_t)NE * NT * ND);

    cudaFuncSetAttribute(glu_mma_kernel,
                         cudaFuncAttributeMaxDynamicSharedMemorySize, 98304);
    cudaFuncSetAttribute(out_mma_kernel,
                         cudaFuncAttributeMaxDynamicSharedMemorySize, 98304);

    // grid.x = m-tiles (fastest) so the 8 sibling m-blocks of a strip run
    // concurrently: their redundant strip converts dedup in L2, and they
    // share B slabs in L2 during the mainloop.
    glu_mma_kernel<<<dim3(NT / 128, NI / 64, NE), 256, 98304>>>(gw, iw);
    out_mma_kernel<<<dim3(NT / 128, ND / 128, NE), 256, 98304>>>(ow, out);
}

// round 13
// speedup vs baseline: 1.3670x; 1.3670x over previous
#include <cuda_runtime.h>
#include <cuda_fp16.h>
#include <cstdint>

// Problem dims (fixed by the reference)
#define NE 8
#define NT 1024
#define ND 2048
#define NI 4096

// ---------------------------------------------------------------------------
// __device__ scratch (alloc-free rule): fp16 copies of inputs + intermediate H
// g_owh is filled by GEMM1's distributed prologue (non-redundant chunks).
// ---------------------------------------------------------------------------
__device__ __half g_xh [(size_t)NE * NT * ND];   //  32 MB
__device__ __half g_gwh[(size_t)NE * ND * NI];   // 134 MB
__device__ __half g_iwh[(size_t)NE * ND * NI];   // 134 MB
__device__ __half g_owh[(size_t)NE * NI * ND];   // 134 MB
__device__ __half g_H  [(size_t)NE * NT * NI];   //  67 MB

// ---------------------------------------------------------------------------
// PTX helpers (baseline sm_80+ instructions only — compute_103-safe)
// ---------------------------------------------------------------------------
__device__ __forceinline__ uint32_t smem_u32(const void* p) {
    uint32_t a;
    asm("{ .reg .u64 t; cvta.to.shared.u64 t, %1; cvt.u32.u64 %0, t; }"
        : "=r"(a) : "l"(p));
    return a;
}
__device__ __forceinline__ void cp16(uint32_t saddr, const void* g) {
    asm volatile("cp.async.cg.shared.global [%0], [%1], 16;"
                 :: "r"(saddr), "l"(g) : "memory");
}
__device__ __forceinline__ void cp_commit() {
    asm volatile("cp.async.commit_group;" ::: "memory");
}
template <int N> __device__ __forceinline__ void cp_wait() {
    asm volatile("cp.async.wait_group %0;" :: "n"(N) : "memory");
}
__device__ __forceinline__ void ldsm4(uint32_t* r, uint32_t a) {
    asm volatile("ldmatrix.sync.aligned.m8n8.x4.shared.b16 {%0,%1,%2,%3}, [%4];"
                 : "=r"(r[0]), "=r"(r[1]), "=r"(r[2]), "=r"(r[3]) : "r"(a));
}
__device__ __forceinline__ void ldsm4t(uint32_t* r, uint32_t a) {
    asm volatile("ldmatrix.sync.aligned.m8n8.x4.trans.shared.b16 {%0,%1,%2,%3}, [%4];"
                 : "=r"(r[0]), "=r"(r[1]), "=r"(r[2]), "=r"(r[3]) : "r"(a));
}
__device__ __forceinline__ void mma16816(float* c, const uint32_t* a,
                                         uint32_t b0, uint32_t b1) {
    asm volatile(
        "mma.sync.aligned.m16n8k16.row.col.f32.f16.f16.f32 "
        "{%0,%1,%2,%3}, {%4,%5,%6,%7}, {%8,%9}, {%0,%1,%2,%3};"
        : "+f"(c[0]), "+f"(c[1]), "+f"(c[2]), "+f"(c[3])
        : "r"(a[0]), "r"(a[1]), "r"(a[2]), "r"(a[3]), "r"(b0), "r"(b1));
}
__device__ __forceinline__ uint32_t h2u(float lo, float hi) {
    __half2 h = __floats2half2_rn(lo, hi);
    return *(uint32_t*)&h;
}
#define SWZ(b) ((b) ^ (((b) >> 3) & 0x70))   // SW128: conflict-free ldmatrix

// ---------------------------------------------------------------------------
// Kernel 0: fp32 -> fp16 conversion (grid-stride; streaming ld/st to spare L2)
// ---------------------------------------------------------------------------
__global__ void cvt_f2h(const float* __restrict__ s, __half* __restrict__ d,
                        size_t n)
{
    size_t i = ((size_t)blockIdx.x * blockDim.x + threadIdx.x) * 8;
    size_t stride = (size_t)gridDim.x * blockDim.x * 8;
    for (; i < n; i += stride) {
        float4 v0 = __ldcs((const float4*)(s + i));
        float4 v1 = __ldcs((const float4*)(s + i + 4));
        uint4 o;
        o.x = h2u(v0.x, v0.y); o.y = h2u(v0.z, v0.w);
        o.z = h2u(v1.x, v1.y); o.w = h2u(v1.z, v1.w);
        __stcs((uint4*)(d + i), o);
    }
}

// ===========================================================================
// Kernel 1: fused dual GEMM + GLU (R10 structure: two barriers, loads after
//   MMA block) + distributed, NON-redundant ow conversion overlapped with the
//   pipeline ramp (GEMM1 has ~7 TB/s of DRAM headroom; ow is needed only by
//   GEMM2, which launches after this kernel completes).
//   BM=128, BN=64, BK=64, 3-stage cp.async, 8 warps; smem 96KB; 2 CTAs/SM.
// ===========================================================================
__global__ __launch_bounds__(256, 2)
void glu_mma_kernel(const float* __restrict__ ow)
{
    extern __shared__ char smem[];
    const uint32_t sb = smem_u32(smem);
    const int tid = threadIdx.x, warp = tid >> 5, lane = tid & 31;
    const int wm = warp & 3, wn = warp >> 2;
    const int m0 = blockIdx.x * 128, n0 = blockIdx.y * 64, e = blockIdx.z;

    const __half* Ab = g_xh  + ((size_t)e * NT + m0) * ND;
    const __half* Gb = g_gwh + ((size_t)e * ND) * NI + n0;
    const __half* Ub = g_iwh + ((size_t)e * ND) * NI + n0;

    // per-thread ldmatrix byte offsets (pre-swizzle)
    int aoff[2], boff[2];
    #pragma unroll
    for (int i = 0; i < 2; i++)
        aoff[i] = (wm * 32 + i * 16 + (lane & 15)) * 128 + (lane >> 4) * 16;
    #pragma unroll
    for (int j = 0; j < 2; j++)
        boff[j] = (lane & 15) * 128 + (wn * 32 + j * 16 + (lane >> 4) * 8) * 2;

    float accG[2][4][4] = {}, accU[2][4][4] = {};

    auto load_stage = [&](int kt, int s) {
        const uint32_t sbase = sb + s * 32768;
        const int k0 = kt * 64;
        #pragma unroll
        for (int i = 0; i < 4; i++) {            // A: 128x64 halves
            int f = tid + i * 256, r = f >> 3, c = (f & 7) * 8;
            cp16(sbase + SWZ(r * 128 + c * 2), Ab + (size_t)r * ND + k0 + c);
        }
        #pragma unroll
        for (int i = 0; i < 2; i++) {            // Bg/Bu: 64x64 halves each
            int f = tid + i * 256, r = f >> 3, c = (f & 7) * 8;
            size_t go = (size_t)(k0 + r) * NI + c;
            cp16(sbase + 16384 + SWZ(r * 128 + c * 2), Gb + go);
            cp16(sbase + 24576 + SWZ(r * 128 + c * 2), Ub + go);
        }
    };

    constexpr int KT = ND / 64;   // 32
    load_stage(0, 0); cp_commit();
    load_stage(1, 1); cp_commit();

    // ---- Distributed ow convert: each CTA converts a distinct 16384-element
    //      chunk (64KB read / 32KB write) while the first cp.async stages are
    //      in flight. Non-redundant: linear block id over the 4096-CTA grid.
    {
        const size_t bid = (size_t)blockIdx.x +
                           (size_t)gridDim.x * (blockIdx.y +
                           (size_t)gridDim.y * blockIdx.z);     // 0..4095
        const float* src = ow + bid * 16384;
        __half* dst = g_owh + bid * 16384;
        #pragma unroll
        for (int i = 0; i < 16; i++) {
            int f = (tid + i * 256) * 4;
            float4 v = __ldcs((const float4*)(src + f));
            __stcs((uint2*)(dst + f), make_uint2(h2u(v.x, v.y), h2u(v.z, v.w)));
        }
    }

    for (int kt = 0; kt < KT; ++kt) {
        cp_wait<1>();
        __syncthreads();
        const int s = kt % 3;
        const uint32_t sA = sb + s * 32768, sBg = sA + 16384, sBu = sA + 24576;
        #pragma unroll
        for (int kk = 0; kk < 4; ++kk) {
            uint32_t a[2][4], bg[2][4], bu[2][4];
            #pragma unroll
            for (int i = 0; i < 2; i++) ldsm4(a[i], sA + SWZ(aoff[i] + kk * 32));
            #pragma unroll
            for (int j = 0; j < 2; j++) {
                ldsm4t(bg[j], sBg + SWZ(boff[j] + kk * 2048));
                ldsm4t(bu[j], sBu + SWZ(boff[j] + kk * 2048));
            }
            #pragma unroll
            for (int i = 0; i < 2; i++)
                #pragma unroll
                for (int j = 0; j < 4; j++) {
                    mma16816(accG[i][j], a[i], bg[j >> 1][(j & 1) * 2],
                             bg[j >> 1][(j & 1) * 2 + 1]);
                    mma16816(accU[i][j], a[i], bu[j >> 1][(j & 1) * 2],
                             bu[j >> 1][(j & 1) * 2 + 1]);
                }
        }
        __syncthreads();
        if (kt + 2 < KT) load_stage(kt + 2, (kt + 2) % 3);
        cp_commit();
    }

    // Epilogue: H = silu(G)*U, fp16 store. c-frag: rows lane>>2 (+8), cols 2*(lane&3).
    __half* Hd = g_H + (size_t)e * NT * NI;
    const int rb = m0 + wm * 32 + (lane >> 2);
    const int cb = n0 + wn * 32 + (lane & 3) * 2;
    #pragma unroll
    for (int i = 0; i < 2; i++)
        #pragma unroll
        for (int j = 0; j < 4; j++)
            #pragma unroll
            for (int h = 0; h < 2; h++) {   // h=0: row, h=1: row+8
                float g0 = accG[i][j][h * 2],     u0 = accU[i][j][h * 2];
                float g1 = accG[i][j][h * 2 + 1], u1 = accU[i][j][h * 2 + 1];
                float h0 = (g0 / (1.0f + __expf(-g0))) * u0;
                float h1 = (g1 / (1.0f + __expf(-g1))) * u1;
                size_t off = (size_t)(rb + i * 16 + h * 8) * NI + cb + j * 8;
                *(__half2*)(Hd + off) = __floats2half2_rn(h0, h1);
            }
}

// ===========================================================================
// Kernel 2: out = H @ op.  (R10 structure.)  BM=128, BN=128, BK=64, 3 stages,
//   8 warps (4x2).  smem = 96KB; 2 CTAs/SM via __launch_bounds__(256,2).
// ===========================================================================
__global__ __launch_bounds__(256, 2)
void out_mma_kernel(float* __restrict__ out)
{
    extern __shared__ char smem[];
    const uint32_t sb = smem_u32(smem);
    const int tid = threadIdx.x, warp = tid >> 5, lane = tid & 31;
    const int wm = warp & 3, wn = warp >> 2;
    const int m0 = blockIdx.x * 128, n0 = blockIdx.y * 128, e = blockIdx.z;

    const __half* Ab = g_H   + ((size_t)e * NT + m0) * NI;
    const __half* Bb = g_owh + ((size_t)e * NI) * ND + n0;

    int aoff[2];
    #pragma unroll
    for (int i = 0; i < 2; i++)
        aoff[i] = (wm * 32 + i * 16 + (lane & 15)) * 128 + (lane >> 4) * 16;
    // B: [64 k][128 n] stored as two [64][64] halves (128B rows each)
    int bhalf[4], boff[4];
    #pragma unroll
    for (int j = 0; j < 4; j++) {
        int c = wn * 64 + j * 16 + (lane >> 4) * 8;
        bhalf[j] = (c >> 6) * 8192;
        boff[j]  = (lane & 15) * 128 + (c & 63) * 2;
    }

    float acc[2][8][4] = {};

    auto load_stage = [&](int kt, int s) {
        const uint32_t sbase = sb + s * 32768;
        const int k0 = kt * 64;
        #pragma unroll
        for (int i = 0; i < 4; i++) {            // A: 128x64
            int f = tid + i * 256, r = f >> 3, c = (f & 7) * 8;
            cp16(sbase + SWZ(r * 128 + c * 2), Ab + (size_t)r * NI + k0 + c);
        }
        #pragma unroll
        for (int i = 0; i < 4; i++) {            // B: 64x128
            int f = tid + i * 256, r = f >> 4, c = (f & 15) * 8;
            cp16(sbase + 16384 + (c >> 6) * 8192 + SWZ(r * 128 + (c & 63) * 2),
                 Bb + (size_t)(k0 + r) * ND + c);
        }
    };

    constexpr int KT = NI / 64;   // 64
    load_stage(0, 0); cp_commit();
    load_stage(1, 1); cp_commit();

    for (int kt = 0; kt < KT; ++kt) {
        cp_wait<1>();
        __syncthreads();
        const int s = kt % 3;
        const uint32_t sA = sb + s * 32768, sB = sA + 16384;
        #pragma unroll
        for (int kk = 0; kk < 4; ++kk) {
            uint32_t a[2][4], b[4][4];
            #pragma unroll
            for (int i = 0; i < 2; i++) ldsm4(a[i], sA + SWZ(aoff[i] + kk * 32));
            #pragma unroll
            for (int j = 0; j < 4; j++)
                ldsm4t(b[j], sB + bhalf[j] + SWZ(boff[j] + kk * 2048));
            #pragma unroll
            for (int i = 0; i < 2; i++)
                #pragma unroll
                for (int j = 0; j < 8; j++)
                    mma16816(acc[i][j], a[i], b[j >> 1][(j & 1) * 2],
                             b[j >> 1][(j & 1) * 2 + 1]);
        }
        __syncthreads();
        if (kt + 2 < KT) load_stage(kt + 2, (kt + 2) % 3);
        cp_commit();
    }

    // Epilogue: fp32 stores
    float* Od = out + (size_t)e * NT * ND;
    const int rb = m0 + wm * 32 + (lane >> 2);
    const int cb = n0 + wn * 64 + (lane & 3) * 2;
    #pragma unroll
    for (int i = 0; i < 2; i++)
        #pragma unroll
        for (int j = 0; j < 8; j++)
            #pragma unroll
            for (int h = 0; h < 2; h++) {
                size_t off = (size_t)(rb + i * 16 + h * 8) * ND + cb + j * 8;
                float2 v = make_float2(acc[i][j][h * 2], acc[i][j][h * 2 + 1]);
                *(float2*)(Od + off) = v;
            }
}

// ---------------------------------------------------------------------------
// Harness entry. Inputs: x, gate_proj, inner_proj, output_proj (all fp32).
// Sequence: cvt x/gw/iw -> GEMM1 (GLU; converts ow in distributed chunks,
// overlapped) -> GEMM2. All graph-capturable, no allocations.
// ---------------------------------------------------------------------------
extern "C" void kernel_launch(void* const* d_in, const int* in_sizes, int n_in,
                              void* d_out, int out_size)
{
    const float* x  = (const float*)d_in[0];
    const float* gw = (const float*)d_in[1];
    const float* iw = (const float*)d_in[2];
    const float* ow = (const float*)d_in[3];
    float* out = (float*)d_out;

    __half *xh, *gwh, *iwh;
    cudaGetSymbolAddress((void**)&xh,  g_xh);
    cudaGetSymbolAddress((void**)&gwh, g_gwh);
    cudaGetSymbolAddress((void**)&iwh, g_iwh);

    cvt_f2h<<<2048, 256>>>(x,  xh,  (size_t)NE * NT * ND);
    cvt_f2h<<<2048, 256>>>(gw, gwh, (size_t)NE * ND * NI);
    cvt_f2h<<<2048, 256>>>(iw, iwh, (size_t)NE * ND * NI);

    cudaFuncSetAttribute(glu_mma_kernel,
                         cudaFuncAttributeMaxDynamicSharedMemorySize, 98304);
    cudaFuncSetAttribute(out_mma_kernel,
                         cudaFuncAttributeMaxDynamicSharedMemorySize, 98304);

    // grid.x = m-tiles (fastest) so concurrent CTAs share B slabs in L2
    glu_mma_kernel<<<dim3(NT / 128, NI / 64, NE), 256, 98304>>>(ow);
    out_mma_kernel<<<dim3(NT / 128, ND / 128, NE), 256, 98304>>>(out);
}